// round 10
// baseline (speedup 1.0000x reference)
#include <cuda_runtime.h>
#include <cuda_bf16.h>
#include <cstdint>
#include <math.h>

#define N_SPK 2048
#define M_UTT 16
#define D_EMB 512
#define NM (N_SPK * M_UTT)
#define EPSF 1e-8f
#define GRID_GEMM 152                  // GB300: 152 SMs, persistent 1 CTA/SM
#define NUNITS 2048                    // 256 mtiles x 8 ntiles

// ---------------- scratch (allocation-free rule: __device__ globals) -------
__device__ __nv_bfloat16 g_vnb[NM * D_EMB];     // normalized utterances, bf16
__device__ __nv_bfloat16 g_Cnb[N_SPK * D_EMB];  // normalized centroids,  bf16
__device__ float g_sdiag[NM];                   // cos(C_min[j], v_j) fp32-exact
__device__ float g_sself[NM];                   // dot of bf16-rounded Cn,vn
__device__ float g_colsum[NM];                  // sum_n exp(w*(S[n,j]-1))
__device__ unsigned int g_done = 0;             // completion counter (reset by last CTA)

// ---------------- helpers ---------------------------------------------------
__device__ __forceinline__ uint32_t smem_u32(const void* p) {
    uint32_t a;
    asm("{ .reg .u64 t; cvta.to.shared.u64 t, %1; cvt.u32.u64 %0, t; }" : "=r"(a) : "l"(p));
    return a;
}
__device__ __forceinline__ void cp16(uint32_t s, const void* g) {
    asm volatile("cp.async.cg.shared.global [%0], [%1], 16;" :: "r"(s), "l"(g) : "memory");
}
__device__ __forceinline__ void cp_commit() { asm volatile("cp.async.commit_group;" ::: "memory"); }
__device__ __forceinline__ void cp_wait1()  { asm volatile("cp.async.wait_group 1;" ::: "memory"); }
__device__ __forceinline__ float ex2a(float x) {
    float r; asm("ex2.approx.f32 %0, %1;" : "=f"(r) : "f"(x)); return r;
}
#define MMA_BF16(d, a0, a1, a2, a3, b0, b1)                                   \
    asm volatile(                                                             \
        "mma.sync.aligned.m16n8k16.row.col.f32.bf16.bf16.f32 "                \
        "{%0,%1,%2,%3}, {%4,%5,%6,%7}, {%8,%9}, {%0,%1,%2,%3};"               \
        : "+f"(d[0]), "+f"(d[1]), "+f"(d[2]), "+f"(d[3])                      \
        : "r"(a0), "r"(a1), "r"(a2), "r"(a3), "r"(b0), "r"(b1))
#define LDSM_X4(r0, r1, r2, r3, addr)                                         \
    asm volatile(                                                             \
        "ldmatrix.sync.aligned.m8n8.x4.shared.b16 {%0,%1,%2,%3}, [%4];"       \
        : "=r"(r0), "=r"(r1), "=r"(r2), "=r"(r3) : "r"(addr))

// ---------------- prep: per-speaker normalize + diag terms -----------------
__global__ __launch_bounds__(256) void prep_kernel(const float* __restrict__ v) {
    __shared__ float sv[M_UTT * D_EMB];
    __shared__ float red[8][33];
    __shared__ float fin[33];

    const int tid = threadIdx.x;
    const int n = blockIdx.x;

    if (tid < 16) g_colsum[n * 16 + tid] = 0.0f;   // zero for gemm atomics

    {
        const float4* src = (const float4*)(v + (size_t)n * M_UTT * D_EMB);
        float4* dst = (float4*)sv;
        #pragma unroll
        for (int i = 0; i < (M_UTT * D_EMB / 4) / 256; i++)
            dst[tid + i * 256] = src[tid + i * 256];
    }
    __syncthreads();

    float s0 = 0.0f, s1 = 0.0f;
    #pragma unroll
    for (int m = 0; m < M_UTT; m++) {
        s0 += sv[m * D_EMB + tid];
        s1 += sv[m * D_EMB + tid + 256];
    }

    float vals[33];
    #pragma unroll
    for (int m = 0; m < M_UTT; m++) {
        float x0 = sv[m * D_EMB + tid];
        float x1 = sv[m * D_EMB + tid + 256];
        vals[m]      = x0 * x0 + x1 * x1;
        vals[16 + m] = s0 * x0 + s1 * x1;
    }
    vals[32] = s0 * s0 + s1 * s1;

    #pragma unroll
    for (int i = 0; i < 33; i++) {
        float x = vals[i];
        #pragma unroll
        for (int o = 16; o > 0; o >>= 1) x += __shfl_xor_sync(0xffffffffu, x, o);
        vals[i] = x;
    }
    const int warp = tid >> 5, lane = tid & 31;
    if (lane == 0) {
        #pragma unroll
        for (int i = 0; i < 33; i++) red[warp][i] = vals[i];
    }
    __syncthreads();
    if (tid < 33) {
        float x = 0.0f;
        #pragma unroll
        for (int w = 0; w < 8; w++) x += red[w][tid];
        fin[tid] = x;
    }
    __syncthreads();

    const float ss = fin[32];
    const float cinv = 1.0f / fmaxf(sqrtf(ss), (float)M_UTT * EPSF);

    __nv_bfloat16 cb0 = __float2bfloat16(s0 * cinv);
    __nv_bfloat16 cb1 = __float2bfloat16(s1 * cinv);
    g_Cnb[n * D_EMB + tid]       = cb0;
    g_Cnb[n * D_EMB + tid + 256] = cb1;
    const float fc0 = __bfloat162float(cb0);
    const float fc1 = __bfloat162float(cb1);

    float sfp[16];
    #pragma unroll
    for (int m = 0; m < M_UTT; m++) {
        float rv = 1.0f / fmaxf(sqrtf(fin[m]), EPSF);
        __nv_bfloat16 vb0 = __float2bfloat16(sv[m * D_EMB + tid] * rv);
        __nv_bfloat16 vb1 = __float2bfloat16(sv[m * D_EMB + tid + 256] * rv);
        size_t base = (size_t)(n * M_UTT + m) * D_EMB;
        g_vnb[base + tid]       = vb0;
        g_vnb[base + tid + 256] = vb1;
        sfp[m] = fc0 * __bfloat162float(vb0) + fc1 * __bfloat162float(vb1);
    }

    #pragma unroll
    for (int m = 0; m < 16; m++) {
        float x = sfp[m];
        #pragma unroll
        for (int o = 16; o > 0; o >>= 1) x += __shfl_xor_sync(0xffffffffu, x, o);
        sfp[m] = x;
    }
    if (lane == 0) {
        #pragma unroll
        for (int m = 0; m < 16; m++) red[warp][m] = sfp[m];
    }
    __syncthreads();
    if (tid < 16) {
        float x = 0.0f;
        #pragma unroll
        for (int w = 0; w < 8; w++) x += red[w][tid];
        g_sself[n * M_UTT + tid] = x;

        float sq  = fin[tid];
        float dsv = fin[16 + tid];
        float nv  = fmaxf(sqrtf(sq), EPSF);
        float cm2 = fmaxf(ss - 2.0f * dsv + sq, 0.0f);
        const float invMm1 = 1.0f / (float)(M_UTT - 1);
        float ncm = fmaxf(sqrtf(cm2) * invMm1, EPSF);
        g_sdiag[n * M_UTT + tid] = ((dsv - sq) * invMm1) / (ncm * nv);
    }
}

// ---------------- persistent GEMM + fused exp rowsum + fused loss ----------
// XOR-swizzled smem (no pads): A 128x1024B, B ring-of-3 of 256x128B.
// One __syncthreads per K64 chunk. Last CTA computes the final loss.
#define A_ROWB   1024                      // bytes per A row (512 bf16)
#define SA_BYTES (128 * A_ROWB)            // 131072
#define SB_BYTES 32768                     // 256 rows x 128B, per ring slot
#define SB_OFF   SA_BYTES
#define SRED_OFF (SB_OFF + 3 * SB_BYTES)   // 229376
#define SMEM_SZ  (SRED_OFF + 4 * 128 * 4)  // 231424

__global__ __launch_bounds__(256, 1) void gemm_lse_kernel(const float* __restrict__ wp,
                                                          float* __restrict__ outp) {
    extern __shared__ char smem[];
    const uint32_t sbase = smem_u32(smem);
    float* red = (float*)(smem + SRED_OFF);

    const int tid = threadIdx.x;
    const int lane = tid & 31, wid = tid >> 5;
    const int warpM = wid & 1;
    const int warpN = wid >> 1;
    const int qg = lane >> 2, t = lane & 3;
    const int mat = lane >> 3, rr = lane & 7;   // ldmatrix lane roles

    const int start = (int)(((long long)blockIdx.x * NUNITS) / GRID_GEMM);
    const int end   = (int)(((long long)(blockIdx.x + 1) * NUNITS) / GRID_GEMM);

    const float wv = *wp;
    const float c1 = wv * 1.44269504f;
    const float c0 = -c1;

    // Swizzled per-lane ldmatrix constants. For every lane, row%8 == rr, so
    // swizzled 16B-col = (rawcol ^ rr) with rawcol = s*2 + matbit.
    uint32_t aBase[4];                 // per i: row = warpM*64+i*16+(mat&1)*8+rr
    #pragma unroll
    for (int i = 0; i < 4; i++)
        aBase[i] = sbase + (uint32_t)(warpM * 64 + i * 16 + (mat & 1) * 8 + rr) * A_ROWB;
    uint32_t bBase[4];                 // per j2: row = warpN*64+j2*16+(mat>>1)*8+rr
    #pragma unroll
    for (int j2 = 0; j2 < 4; j2++)
        bBase[j2] = sbase + SB_OFF
                  + (uint32_t)(warpN * 64 + j2 * 16 + (mat >> 1) * 8 + rr) * 128;
    uint32_t aSw[4], bSw[4];
    #pragma unroll
    for (int s = 0; s < 4; s++) {
        aSw[s] = (uint32_t)(((s * 2 + (mat >> 1)) ^ rr) * 16);
        bSw[s] = (uint32_t)(((s * 2 + (mat & 1)) ^ rr) * 16);
    }

    auto loadB = [&](int ntile, int kc, int slot) {
        const __nv_bfloat16* bsrc = g_Cnb + (size_t)(ntile * 256) * D_EMB + kc * 64;
        const uint32_t bb = sbase + SB_OFF + slot * SB_BYTES;
        #pragma unroll
        for (int i = 0; i < 8; i++) {
            int flat = tid + 256 * i;          // 0..2047
            int row = flat >> 3, k8 = flat & 7;
            int sk = k8 ^ (row & 7);
            cp16(bb + row * 128 + sk * 16, bsrc + (size_t)row * D_EMB + k8 * 8);
        }
    };

    float acc[4][8][4];
    #pragma unroll
    for (int i = 0; i < 4; i++)
        #pragma unroll
        for (int j = 0; j < 8; j++)
            #pragma unroll
            for (int r = 0; r < 4; r++) acc[i][j][r] = 0.0f;

    for (int g = start; g < end; ) {
        const int mt = g >> 3;
        const int run_end = min(end, (mt + 1) << 3);
        const int cnt = (run_end - g) * 8;

        // ---- stage A for this mtile (swizzled); grouped with B chunk 0 ----
        {
            const __nv_bfloat16* vsrc = g_vnb + (size_t)(mt * 128) * D_EMB;
            #pragma unroll 8
            for (int i = 0; i < 32; i++) {
                int flat = tid + 256 * i;      // 0..8191
                int row = flat >> 6, cc = flat & 63;
                int scc = cc ^ (row & 7);
                cp16(sbase + row * A_ROWB + scc * 16,
                     vsrc + (size_t)row * D_EMB + cc * 8);
            }
        }
        loadB(g & 7, 0, 0); cp_commit();
        loadB(g & 7, 1, 1); cp_commit();

        float rs[4][2] = {{0,0},{0,0},{0,0},{0,0}};
        int slot = 0, slot2 = 2;               // c%3 and (c+2)%3

        #pragma unroll 1
        for (int c = 0; c < cnt; c++) {
            cp_wait1();                        // chunk c resident
            __syncthreads();                   // everyone done with slot2's old data

            if (c + 2 < cnt) {                 // prefetch c+2 into free slot
                const int c2 = c + 2;
                loadB((g + (c2 >> 3)) & 7, c2 & 7, slot2);
            }
            cp_commit();                       // one group per iteration

            const uint32_t kcB = (uint32_t)(c & 7) * 128;
            const uint32_t bOff = (uint32_t)slot * SB_BYTES;

            #pragma unroll
            for (int s = 0; s < 4; s++) {
                uint32_t ra[4][4];
                #pragma unroll
                for (int i = 0; i < 4; i++)
                    LDSM_X4(ra[i][0], ra[i][1], ra[i][2], ra[i][3],
                            aBase[i] + kcB + aSw[s]);
                #pragma unroll
                for (int j2 = 0; j2 < 4; j2++) {
                    uint32_t rb0, rb1, rb2, rb3;
                    LDSM_X4(rb0, rb1, rb2, rb3, bBase[j2] + bOff + bSw[s]);
                    #pragma unroll
                    for (int i = 0; i < 4; i++) {
                        MMA_BF16(acc[i][2 * j2],     ra[i][0], ra[i][1], ra[i][2], ra[i][3], rb0, rb1);
                        MMA_BF16(acc[i][2 * j2 + 1], ra[i][0], ra[i][1], ra[i][2], ra[i][3], rb2, rb3);
                    }
                }
            }

            if ((c & 7) == 7) {                // unit done: exp rowsums
                #pragma unroll
                for (int i = 0; i < 4; i++) {
                    float a0 = 0.0f, a1 = 0.0f;
                    #pragma unroll
                    for (int j = 0; j < 8; j++) {
                        a0 += ex2a(fmaf(acc[i][j][0], c1, c0)) + ex2a(fmaf(acc[i][j][1], c1, c0));
                        a1 += ex2a(fmaf(acc[i][j][2], c1, c0)) + ex2a(fmaf(acc[i][j][3], c1, c0));
                        acc[i][j][0] = acc[i][j][1] = acc[i][j][2] = acc[i][j][3] = 0.0f;
                    }
                    rs[i][0] += a0;
                    rs[i][1] += a1;
                }
            }

            slot = (slot == 2) ? 0 : slot + 1;
            slot2 = (slot2 == 2) ? 0 : slot2 + 1;
        }

        // ---- flush rowsums for this mtile run -----------------------------
        #pragma unroll
        for (int i = 0; i < 4; i++)
            #pragma unroll
            for (int r = 0; r < 2; r++) {
                float x = rs[i][r];
                x += __shfl_xor_sync(0xffffffffu, x, 1);
                x += __shfl_xor_sync(0xffffffffu, x, 2);
                rs[i][r] = x;
            }
        __syncthreads();                       // all LDSM reads of A/B done before red reuse
        if (t == 0) {
            #pragma unroll
            for (int i = 0; i < 4; i++)
                #pragma unroll
                for (int r = 0; r < 2; r++)
                    red[warpN * 128 + warpM * 64 + i * 16 + r * 8 + qg] = rs[i][r];
        }
        __syncthreads();
        if (tid < 128)
            atomicAdd(&g_colsum[mt * 128 + tid],
                      (red[tid] + red[128 + tid]) + (red[256 + tid] + red[384 + tid]));
        __syncthreads();                       // red/A reuse next run

        g = run_end;
    }

    // ---- fused final loss: last CTA to finish computes everything ---------
    __shared__ unsigned int srank;
    __shared__ float lsm[8];
    if (tid == 0) {
        __threadfence();
        srank = atomicAdd(&g_done, 1u);
    }
    __syncthreads();
    if (srank == GRID_GEMM - 1) {
        __threadfence();                       // see all CTAs' colsum atomics
        float L = 0.0f;
        #pragma unroll 4
        for (int j = tid; j < NM; j += 256) {
            float sd = g_sdiag[j];
            float sf = g_sself[j];
            float cs = g_colsum[j] - ex2a(fmaf(sf, c1, c0)) + ex2a(fmaf(sd, c1, c0));
            L += wv * (1.0f - sd) + __logf(cs);
        }
        #pragma unroll
        for (int o = 16; o > 0; o >>= 1) L += __shfl_xor_sync(0xffffffffu, L, o);
        if (lane == 0) lsm[wid] = L;
        __syncthreads();
        if (tid == 0) {
            float tt = 0.0f;
            #pragma unroll
            for (int w = 0; w < 8; w++) tt += lsm[w];
            *outp = tt;
            g_done = 0;                        // reset for next graph replay
        }
    }
}

// ---------------------------------------------------------------------------
extern "C" void kernel_launch(void* const* d_in, const int* in_sizes, int n_in,
                              void* d_out, int out_size) {
    const float* v  = (const float*)d_in[0];   // [NM, D] fp32
    const float* wp = (const float*)d_in[1];   // scalar w (b cancels analytically)
    float* out = (float*)d_out;

    cudaFuncSetAttribute(gemm_lse_kernel,
                         cudaFuncAttributeMaxDynamicSharedMemorySize, SMEM_SZ);

    prep_kernel<<<N_SPK, 256>>>(v);
    gemm_lse_kernel<<<GRID_GEMM, 256, SMEM_SZ>>>(wp, out);
}

// round 11
// speedup vs baseline: 1.0271x; 1.0271x over previous
#include <cuda_runtime.h>
#include <cuda_bf16.h>
#include <cstdint>
#include <math.h>

#define N_SPK 2048
#define M_UTT 16
#define D_EMB 512
#define NM (N_SPK * M_UTT)
#define EPSF 1e-8f
#define GRID_GEMM 304                  // 2 persistent CTAs per SM (152 SMs)
#define NUNITS 4096                    // 256 mtiles x 16 ntiles (128x128 units)

// ---------------- scratch (allocation-free rule: __device__ globals) -------
__device__ __nv_bfloat16 g_vnb[NM * D_EMB];     // normalized utterances, bf16
__device__ __nv_bfloat16 g_Cnb[N_SPK * D_EMB];  // normalized centroids,  bf16
__device__ float g_sdiag[NM];                   // cos(C_min[j], v_j) fp32-exact
__device__ float g_sself[NM];                   // dot of bf16-rounded Cn,vn
__device__ float g_colsum[NM];                  // sum_n exp(w*(S[n,j]-1))
__device__ unsigned int g_done = 0;             // completion counter

// ---------------- helpers ---------------------------------------------------
__device__ __forceinline__ uint32_t smem_u32(const void* p) {
    uint32_t a;
    asm("{ .reg .u64 t; cvta.to.shared.u64 t, %1; cvt.u32.u64 %0, t; }" : "=r"(a) : "l"(p));
    return a;
}
__device__ __forceinline__ void cp16(uint32_t s, const void* g) {
    asm volatile("cp.async.cg.shared.global [%0], [%1], 16;" :: "r"(s), "l"(g) : "memory");
}
__device__ __forceinline__ void cp_commit() { asm volatile("cp.async.commit_group;" ::: "memory"); }
__device__ __forceinline__ void cp_wait1()  { asm volatile("cp.async.wait_group 1;" ::: "memory"); }
__device__ __forceinline__ float ex2a(float x) {
    float r; asm("ex2.approx.f32 %0, %1;" : "=f"(r) : "f"(x)); return r;
}
#define MMA_BF16(d, a0, a1, a2, a3, b0, b1)                                   \
    asm volatile(                                                             \
        "mma.sync.aligned.m16n8k16.row.col.f32.bf16.bf16.f32 "                \
        "{%0,%1,%2,%3}, {%4,%5,%6,%7}, {%8,%9}, {%0,%1,%2,%3};"               \
        : "+f"(d[0]), "+f"(d[1]), "+f"(d[2]), "+f"(d[3])                      \
        : "r"(a0), "r"(a1), "r"(a2), "r"(a3), "r"(b0), "r"(b1))
#define LDSM_X4(r0, r1, r2, r3, addr)                                         \
    asm volatile(                                                             \
        "ldmatrix.sync.aligned.m8n8.x4.shared.b16 {%0,%1,%2,%3}, [%4];"       \
        : "=r"(r0), "=r"(r1), "=r"(r2), "=r"(r3) : "r"(addr))

// ---------------- prep: per-speaker normalize + diag terms -----------------
__global__ __launch_bounds__(256) void prep_kernel(const float* __restrict__ v) {
    __shared__ float sv[M_UTT * D_EMB];
    __shared__ float red[8][33];
    __shared__ float fin[33];

    const int tid = threadIdx.x;
    const int n = blockIdx.x;

    if (tid < 16) g_colsum[n * 16 + tid] = 0.0f;   // zero for gemm atomics

    {
        const float4* src = (const float4*)(v + (size_t)n * M_UTT * D_EMB);
        float4* dst = (float4*)sv;
        #pragma unroll
        for (int i = 0; i < (M_UTT * D_EMB / 4) / 256; i++)
            dst[tid + i * 256] = src[tid + i * 256];
    }
    __syncthreads();

    float s0 = 0.0f, s1 = 0.0f;
    #pragma unroll
    for (int m = 0; m < M_UTT; m++) {
        s0 += sv[m * D_EMB + tid];
        s1 += sv[m * D_EMB + tid + 256];
    }

    float vals[33];
    #pragma unroll
    for (int m = 0; m < M_UTT; m++) {
        float x0 = sv[m * D_EMB + tid];
        float x1 = sv[m * D_EMB + tid + 256];
        vals[m]      = x0 * x0 + x1 * x1;
        vals[16 + m] = s0 * x0 + s1 * x1;
    }
    vals[32] = s0 * s0 + s1 * s1;

    #pragma unroll
    for (int i = 0; i < 33; i++) {
        float x = vals[i];
        #pragma unroll
        for (int o = 16; o > 0; o >>= 1) x += __shfl_xor_sync(0xffffffffu, x, o);
        vals[i] = x;
    }
    const int warp = tid >> 5, lane = tid & 31;
    if (lane == 0) {
        #pragma unroll
        for (int i = 0; i < 33; i++) red[warp][i] = vals[i];
    }
    __syncthreads();
    if (tid < 33) {
        float x = 0.0f;
        #pragma unroll
        for (int w = 0; w < 8; w++) x += red[w][tid];
        fin[tid] = x;
    }
    __syncthreads();

    const float ss = fin[32];
    const float cinv = 1.0f / fmaxf(sqrtf(ss), (float)M_UTT * EPSF);

    __nv_bfloat16 cb0 = __float2bfloat16(s0 * cinv);
    __nv_bfloat16 cb1 = __float2bfloat16(s1 * cinv);
    g_Cnb[n * D_EMB + tid]       = cb0;
    g_Cnb[n * D_EMB + tid + 256] = cb1;
    const float fc0 = __bfloat162float(cb0);
    const float fc1 = __bfloat162float(cb1);

    float sfp[16];
    #pragma unroll
    for (int m = 0; m < M_UTT; m++) {
        float rv = 1.0f / fmaxf(sqrtf(fin[m]), EPSF);
        __nv_bfloat16 vb0 = __float2bfloat16(sv[m * D_EMB + tid] * rv);
        __nv_bfloat16 vb1 = __float2bfloat16(sv[m * D_EMB + tid + 256] * rv);
        size_t base = (size_t)(n * M_UTT + m) * D_EMB;
        g_vnb[base + tid]       = vb0;
        g_vnb[base + tid + 256] = vb1;
        sfp[m] = fc0 * __bfloat162float(vb0) + fc1 * __bfloat162float(vb1);
    }

    #pragma unroll
    for (int m = 0; m < 16; m++) {
        float x = sfp[m];
        #pragma unroll
        for (int o = 16; o > 0; o >>= 1) x += __shfl_xor_sync(0xffffffffu, x, o);
        sfp[m] = x;
    }
    if (lane == 0) {
        #pragma unroll
        for (int m = 0; m < 16; m++) red[warp][m] = sfp[m];
    }
    __syncthreads();
    if (tid < 16) {
        float x = 0.0f;
        #pragma unroll
        for (int w = 0; w < 8; w++) x += red[w][tid];
        g_sself[n * M_UTT + tid] = x;

        float sq  = fin[tid];
        float dsv = fin[16 + tid];
        float nv  = fmaxf(sqrtf(sq), EPSF);
        float cm2 = fmaxf(ss - 2.0f * dsv + sq, 0.0f);
        const float invMm1 = 1.0f / (float)(M_UTT - 1);
        float ncm = fmaxf(sqrtf(cm2) * invMm1, EPSF);
        g_sdiag[n * M_UTT + tid] = ((dsv - sq) * invMm1) / (ncm * nv);
    }
}

// ---------------- persistent GEMM, 2 CTAs/SM, warp m64n32 -------------------
// Unit = 128 utt x 128 spk. A and B both streamed per K64 chunk (16KB each),
// double-buffered, padded pitch 144B (proven conflict-free). CTA 256 thr,
// 8 warps = 2(M) x 4(N). 64 accs/thread -> <=128 regs -> 2 CTAs/SM.
#define PITCHB   144
#define AB_OFF   (128 * PITCHB)            // B at +18432 within slot
#define SLOT_B   (256 * PITCHB)            // 36864 per slot (A+B)
#define SRED_OFF (2 * SLOT_B)              // 73728
#define SMEM_SZ  (SRED_OFF + 4 * 128 * 4)  // 75776 -> 2 CTAs/SM fits

__global__ __launch_bounds__(256, 2) void gemm_lse_kernel(const float* __restrict__ wp,
                                                          float* __restrict__ outp) {
    extern __shared__ char smem[];
    const uint32_t sbase = smem_u32(smem);
    float* red = (float*)(smem + SRED_OFF);

    const int tid = threadIdx.x;
    const int lane = tid & 31, wid = tid >> 5;
    const int warpM = wid & 1;            // 2 warps over M=128
    const int warpN = wid >> 1;           // 4 warps over N=128 (n32 each)
    const int qg = lane >> 2, t = lane & 3;
    const int mat = lane >> 3, rr = lane & 7;

    const int start = (int)(((long long)blockIdx.x * NUNITS) / GRID_GEMM);
    const int end   = (int)(((long long)(blockIdx.x + 1) * NUNITS) / GRID_GEMM);

    const float wv = *wp;
    const float c1 = wv * 1.44269504f;
    const float c0 = -c1;

    // ldmatrix per-lane addresses (R8-proven mapping, pitch 144)
    uint32_t aAddr[4];                    // i: (r0 rows0-7,k0-7)(r1 rows8-15,k0-7)(r2 .. k8-15)(r3 ..)
    #pragma unroll
    for (int i = 0; i < 4; i++)
        aAddr[i] = sbase + (uint32_t)(warpM * 64 + i * 16 + (mat & 1) * 8 + rr) * PITCHB
                 + (uint32_t)(mat >> 1) * 16;
    uint32_t bAddr[2];                    // j2: (r0 n-rows,k0-7)(r1 ..,k8-15)(r2 n+8,k0-7)(r3 ..)
    #pragma unroll
    for (int j2 = 0; j2 < 2; j2++)
        bAddr[j2] = sbase + AB_OFF
                  + (uint32_t)(warpN * 32 + j2 * 16 + (mat >> 1) * 8 + rr) * PITCHB
                  + (uint32_t)(mat & 1) * 16;

    // load one K64 chunk: A(mt,kc) + B(nt,kc) into slot buf
    auto loadChunk = [&](int mt, int nt, int kc, int buf) {
        const uint32_t so = sbase + (uint32_t)buf * SLOT_B;
        const __nv_bfloat16* asrc = g_vnb + (size_t)(mt * 128) * D_EMB + kc * 64;
        const __nv_bfloat16* bsrc = g_Cnb + (size_t)(nt * 128) * D_EMB + kc * 64;
        #pragma unroll
        for (int i = 0; i < 4; i++) {
            int flat = tid + 256 * i;          // 0..1023
            int row = flat >> 3, k8 = flat & 7;
            cp16(so + row * PITCHB + k8 * 16, asrc + (size_t)row * D_EMB + k8 * 8);
        }
        #pragma unroll
        for (int i = 0; i < 4; i++) {
            int flat = tid + 256 * i;
            int row = flat >> 3, k8 = flat & 7;
            cp16(so + AB_OFF + row * PITCHB + k8 * 16, bsrc + (size_t)row * D_EMB + k8 * 8);
        }
    };

    float acc[4][4][4];                    // 64 accumulators (i=m16 frag, j=n8 frag)
    #pragma unroll
    for (int i = 0; i < 4; i++)
        #pragma unroll
        for (int j = 0; j < 4; j++)
            #pragma unroll
            for (int r = 0; r < 4; r++) acc[i][j][r] = 0.0f;

    for (int g = start; g < end; ) {
        const int mt = g >> 4;
        const int run_end = min(end, (mt + 1) << 4);
        const int cnt = (run_end - g) * 8;     // chunks in this mtile run

        loadChunk(mt, g & 15, 0, 0); cp_commit();
        loadChunk(mt, g & 15, 1, 1); cp_commit();

        float rs[4][2] = {{0,0},{0,0},{0,0},{0,0}};

        #pragma unroll 1
        for (int c = 0; c < cnt; c++) {
            const int buf = c & 1;
            cp_wait1();
            __syncthreads();

            const uint32_t bo = (uint32_t)buf * SLOT_B;

            #pragma unroll
            for (int s = 0; s < 4; s++) {
                uint32_t ra[4][4];
                #pragma unroll
                for (int i = 0; i < 4; i++)
                    LDSM_X4(ra[i][0], ra[i][1], ra[i][2], ra[i][3],
                            aAddr[i] + bo + s * 32);
                #pragma unroll
                for (int j2 = 0; j2 < 2; j2++) {
                    uint32_t rb0, rb1, rb2, rb3;
                    LDSM_X4(rb0, rb1, rb2, rb3, bAddr[j2] + bo + s * 32);
                    #pragma unroll
                    for (int i = 0; i < 4; i++) {
                        MMA_BF16(acc[i][2 * j2],     ra[i][0], ra[i][1], ra[i][2], ra[i][3], rb0, rb1);
                        MMA_BF16(acc[i][2 * j2 + 1], ra[i][0], ra[i][1], ra[i][2], ra[i][3], rb2, rb3);
                    }
                }
            }

            __syncthreads();                   // all warps done with buf
            if (c + 2 < cnt) {
                const int c2 = c + 2;
                loadChunk(mt, (g + (c2 >> 3)) & 15, c2 & 7, buf);
            }
            cp_commit();

            if ((c & 7) == 7) {                // unit done: exp rowsums
                #pragma unroll
                for (int i = 0; i < 4; i++) {
                    float a0 = 0.0f, a1 = 0.0f;
                    #pragma unroll
                    for (int j = 0; j < 4; j++) {
                        a0 += ex2a(fmaf(acc[i][j][0], c1, c0)) + ex2a(fmaf(acc[i][j][1], c1, c0));
                        a1 += ex2a(fmaf(acc[i][j][2], c1, c0)) + ex2a(fmaf(acc[i][j][3], c1, c0));
                        acc[i][j][0] = acc[i][j][1] = acc[i][j][2] = acc[i][j][3] = 0.0f;
                    }
                    rs[i][0] += a0;
                    rs[i][1] += a1;
                }
            }
        }

        // ---- flush rowsums for this mtile run -----------------------------
        #pragma unroll
        for (int i = 0; i < 4; i++)
            #pragma unroll
            for (int r = 0; r < 2; r++) {
                float x = rs[i][r];
                x += __shfl_xor_sync(0xffffffffu, x, 1);
                x += __shfl_xor_sync(0xffffffffu, x, 2);
                rs[i][r] = x;
            }
        if (t == 0) {
            #pragma unroll
            for (int i = 0; i < 4; i++)
                #pragma unroll
                for (int r = 0; r < 2; r++)
                    red[warpN * 128 + warpM * 64 + i * 16 + r * 8 + qg] = rs[i][r];
        }
        __syncthreads();
        if (tid < 128)
            atomicAdd(&g_colsum[mt * 128 + tid],
                      (red[tid] + red[128 + tid]) + (red[256 + tid] + red[384 + tid]));
        __syncthreads();

        g = run_end;
    }

    // ---- fused final loss: last CTA computes everything -------------------
    __shared__ unsigned int srank;
    __shared__ float lsm[8];
    if (tid == 0) {
        __threadfence();
        srank = atomicAdd(&g_done, 1u);
    }
    __syncthreads();
    if (srank == GRID_GEMM - 1) {
        __threadfence();
        float L = 0.0f;
        #pragma unroll 4
        for (int j = tid; j < NM; j += 256) {
            float sd = g_sdiag[j];
            float sf = g_sself[j];
            float cs = g_colsum[j] - ex2a(fmaf(sf, c1, c0)) + ex2a(fmaf(sd, c1, c0));
            L += wv * (1.0f - sd) + __logf(cs);
        }
        #pragma unroll
        for (int o = 16; o > 0; o >>= 1) L += __shfl_xor_sync(0xffffffffu, L, o);
        if (lane == 0) lsm[wid] = L;
        __syncthreads();
        if (tid == 0) {
            float tt = 0.0f;
            #pragma unroll
            for (int w = 0; w < 8; w++) tt += lsm[w];
            *outp = tt;
            g_done = 0;                        // reset for next graph replay
        }
    }
}

// ---------------------------------------------------------------------------
extern "C" void kernel_launch(void* const* d_in, const int* in_sizes, int n_in,
                              void* d_out, int out_size) {
    const float* v  = (const float*)d_in[0];   // [NM, D] fp32
    const float* wp = (const float*)d_in[1];   // scalar w (b cancels analytically)
    float* out = (float*)d_out;

    cudaFuncSetAttribute(gemm_lse_kernel,
                         cudaFuncAttributeMaxDynamicSharedMemorySize, SMEM_SZ);

    prep_kernel<<<N_SPK, 256>>>(v);
    gemm_lse_kernel<<<GRID_GEMM, 256, SMEM_SZ>>>(wp, out);
}

// round 12
// speedup vs baseline: 1.0329x; 1.0057x over previous
#include <cuda_runtime.h>
#include <cuda_bf16.h>
#include <cstdint>
#include <math.h>

#define N_SPK 2048
#define M_UTT 16
#define D_EMB 512
#define NM (N_SPK * M_UTT)
#define EPSF 1e-8f
#define GRID_GEMM 152                  // GB300: 152 SMs, persistent 1 CTA/SM
#define NUNITS 2048                    // 256 mtiles x 8 ntiles

// ---------------- scratch (allocation-free rule: __device__ globals) -------
__device__ __nv_bfloat16 g_vnb[NM * D_EMB];     // normalized utterances, bf16
__device__ __nv_bfloat16 g_Cnb[N_SPK * D_EMB];  // normalized centroids,  bf16
__device__ float g_sdiag[NM];                   // cos(C_min[j], v_j) fp32-exact
__device__ float g_sself[NM];                   // dot of bf16-rounded Cn,vn
__device__ float g_colsum[NM];                  // sum_n exp(w*(S[n,j]-1))
__device__ unsigned int g_done = 0;             // completion counter

// ---------------- helpers ---------------------------------------------------
__device__ __forceinline__ uint32_t smem_u32(const void* p) {
    uint32_t a;
    asm("{ .reg .u64 t; cvta.to.shared.u64 t, %1; cvt.u32.u64 %0, t; }" : "=r"(a) : "l"(p));
    return a;
}
__device__ __forceinline__ void cp16(uint32_t s, const void* g) {
    asm volatile("cp.async.cg.shared.global [%0], [%1], 16;" :: "r"(s), "l"(g) : "memory");
}
__device__ __forceinline__ void cp_commit() { asm volatile("cp.async.commit_group;" ::: "memory"); }
__device__ __forceinline__ void cp_wait1()  { asm volatile("cp.async.wait_group 1;" ::: "memory"); }
__device__ __forceinline__ float ex2a(float x) {
    float r; asm("ex2.approx.f32 %0, %1;" : "=f"(r) : "f"(x)); return r;
}
#define MMA_BF16(d, a0, a1, a2, a3, b0, b1)                                   \
    asm volatile(                                                             \
        "mma.sync.aligned.m16n8k16.row.col.f32.bf16.bf16.f32 "                \
        "{%0,%1,%2,%3}, {%4,%5,%6,%7}, {%8,%9}, {%0,%1,%2,%3};"               \
        : "+f"(d[0]), "+f"(d[1]), "+f"(d[2]), "+f"(d[3])                      \
        : "r"(a0), "r"(a1), "r"(a2), "r"(a3), "r"(b0), "r"(b1))
#define LDSM_X4(r0, r1, r2, r3, addr)                                         \
    asm volatile(                                                             \
        "ldmatrix.sync.aligned.m8n8.x4.shared.b16 {%0,%1,%2,%3}, [%4];"       \
        : "=r"(r0), "=r"(r1), "=r"(r2), "=r"(r3) : "r"(addr))

// ---------------- prep: per-speaker normalize + diag terms -----------------
__global__ __launch_bounds__(256) void prep_kernel(const float* __restrict__ v) {
    __shared__ float sv[M_UTT * D_EMB];
    __shared__ float red[8][33];
    __shared__ float fin[33];

    const int tid = threadIdx.x;
    const int n = blockIdx.x;

    if (tid < 16) g_colsum[n * 16 + tid] = 0.0f;   // zero for gemm atomics

    {
        const float4* src = (const float4*)(v + (size_t)n * M_UTT * D_EMB);
        float4* dst = (float4*)sv;
        #pragma unroll
        for (int i = 0; i < (M_UTT * D_EMB / 4) / 256; i++)
            dst[tid + i * 256] = src[tid + i * 256];
    }
    __syncthreads();

    float s0 = 0.0f, s1 = 0.0f;
    #pragma unroll
    for (int m = 0; m < M_UTT; m++) {
        s0 += sv[m * D_EMB + tid];
        s1 += sv[m * D_EMB + tid + 256];
    }

    float vals[33];
    #pragma unroll
    for (int m = 0; m < M_UTT; m++) {
        float x0 = sv[m * D_EMB + tid];
        float x1 = sv[m * D_EMB + tid + 256];
        vals[m]      = x0 * x0 + x1 * x1;
        vals[16 + m] = s0 * x0 + s1 * x1;
    }
    vals[32] = s0 * s0 + s1 * s1;

    #pragma unroll
    for (int i = 0; i < 33; i++) {
        float x = vals[i];
        #pragma unroll
        for (int o = 16; o > 0; o >>= 1) x += __shfl_xor_sync(0xffffffffu, x, o);
        vals[i] = x;
    }
    const int warp = tid >> 5, lane = tid & 31;
    if (lane == 0) {
        #pragma unroll
        for (int i = 0; i < 33; i++) red[warp][i] = vals[i];
    }
    __syncthreads();
    if (tid < 33) {
        float x = 0.0f;
        #pragma unroll
        for (int w = 0; w < 8; w++) x += red[w][tid];
        fin[tid] = x;
    }
    __syncthreads();

    const float ss = fin[32];
    const float cinv = 1.0f / fmaxf(sqrtf(ss), (float)M_UTT * EPSF);

    __nv_bfloat16 cb0 = __float2bfloat16(s0 * cinv);
    __nv_bfloat16 cb1 = __float2bfloat16(s1 * cinv);
    g_Cnb[n * D_EMB + tid]       = cb0;
    g_Cnb[n * D_EMB + tid + 256] = cb1;
    const float fc0 = __bfloat162float(cb0);
    const float fc1 = __bfloat162float(cb1);

    float sfp[16];
    #pragma unroll
    for (int m = 0; m < M_UTT; m++) {
        float rv = 1.0f / fmaxf(sqrtf(fin[m]), EPSF);
        __nv_bfloat16 vb0 = __float2bfloat16(sv[m * D_EMB + tid] * rv);
        __nv_bfloat16 vb1 = __float2bfloat16(sv[m * D_EMB + tid + 256] * rv);
        size_t base = (size_t)(n * M_UTT + m) * D_EMB;
        g_vnb[base + tid]       = vb0;
        g_vnb[base + tid + 256] = vb1;
        sfp[m] = fc0 * __bfloat162float(vb0) + fc1 * __bfloat162float(vb1);
    }

    #pragma unroll
    for (int m = 0; m < 16; m++) {
        float x = sfp[m];
        #pragma unroll
        for (int o = 16; o > 0; o >>= 1) x += __shfl_xor_sync(0xffffffffu, x, o);
        sfp[m] = x;
    }
    if (lane == 0) {
        #pragma unroll
        for (int m = 0; m < 16; m++) red[warp][m] = sfp[m];
    }
    __syncthreads();
    if (tid < 16) {
        float x = 0.0f;
        #pragma unroll
        for (int w = 0; w < 8; w++) x += red[w][tid];
        g_sself[n * M_UTT + tid] = x;

        float sq  = fin[tid];
        float dsv = fin[16 + tid];
        float nv  = fmaxf(sqrtf(sq), EPSF);
        float cm2 = fmaxf(ss - 2.0f * dsv + sq, 0.0f);
        const float invMm1 = 1.0f / (float)(M_UTT - 1);
        float ncm = fmaxf(sqrtf(cm2) * invMm1, EPSF);
        g_sdiag[n * M_UTT + tid] = ((dsv - sq) * invMm1) / (ncm * nv);
    }
}

// ---------------- persistent GEMM + fused exp rowsum + fused loss -----------
// R8-proven core: A resident (pitch 1040B), B double-buffered (pitch 144B),
// ldmatrix fragments, 2 syncs/chunk. Last CTA computes the final loss.
#define A_PITCHB 1040                      // bytes per A row (520 bf16)
#define B_PITCHB 144                       // bytes per B row (72 bf16)
#define SA_BYTES (128 * A_PITCHB)          // 133120
#define SB_BYTES (256 * B_PITCHB)          // 36864 per buffer
#define SB_OFF   SA_BYTES
#define SRED_OFF (SB_OFF + 2 * SB_BYTES)   // 206848
#define SMEM_SZ  (SRED_OFF + 4 * 128 * 4)  // 208896

__global__ __launch_bounds__(256, 1) void gemm_lse_kernel(const float* __restrict__ wp,
                                                          float* __restrict__ outp) {
    extern __shared__ char smem[];
    const uint32_t sbase = smem_u32(smem);
    float* red = (float*)(smem + SRED_OFF);

    const int tid = threadIdx.x;
    const int lane = tid & 31, wid = tid >> 5;
    const int warpM = wid & 1;
    const int warpN = wid >> 1;
    const int qg = lane >> 2, t = lane & 3;
    const int mat = lane >> 3, rr = lane & 7;   // ldmatrix address roles

    const int start = (int)(((long long)blockIdx.x * NUNITS) / GRID_GEMM);
    const int end   = (int)(((long long)(blockIdx.x + 1) * NUNITS) / GRID_GEMM);

    const float wv = *wp;
    const float c1 = wv * 1.44269504f;
    const float c0 = -c1;

    // ldmatrix per-lane base addresses (R8-proven mapping)
    uint32_t aAddr[4];
    #pragma unroll
    for (int i = 0; i < 4; i++)
        aAddr[i] = sbase + (uint32_t)(warpM * 64 + i * 16 + (mat & 1) * 8 + rr) * A_PITCHB
                 + (uint32_t)(mat >> 1) * 16;
    uint32_t bAddr[4];
    #pragma unroll
    for (int j2 = 0; j2 < 4; j2++)
        bAddr[j2] = sbase + SB_OFF
                  + (uint32_t)(warpN * 64 + j2 * 16 + (mat >> 1) * 8 + rr) * B_PITCHB
                  + (uint32_t)(mat & 1) * 16;

    auto loadB = [&](int ntile, int kc, int buf) {
        const __nv_bfloat16* bsrc = g_Cnb + (size_t)(ntile * 256) * D_EMB + kc * 64;
        const uint32_t bb = sbase + SB_OFF + buf * SB_BYTES;
        #pragma unroll
        for (int i = 0; i < 8; i++) {
            int flat = tid + 256 * i;
            int row = flat >> 3, k8 = flat & 7;
            cp16(bb + row * B_PITCHB + k8 * 16,
                 bsrc + (size_t)row * D_EMB + k8 * 8);
        }
    };

    float acc[4][8][4];
    #pragma unroll
    for (int i = 0; i < 4; i++)
        #pragma unroll
        for (int j = 0; j < 8; j++)
            #pragma unroll
            for (int r = 0; r < 4; r++) acc[i][j][r] = 0.0f;

    for (int g = start; g < end; ) {
        const int mt = g >> 3;
        const int run_end = min(end, (mt + 1) << 3);
        const int cnt = (run_end - g) * 8;

        // ---- stage A for this mtile (group with B chunk 0) ----------------
        {
            const __nv_bfloat16* vsrc = g_vnb + (size_t)(mt * 128) * D_EMB;
            #pragma unroll 8
            for (int i = 0; i < 32; i++) {
                int flat = tid + 256 * i;
                int row = flat >> 6, cc = flat & 63;
                cp16(sbase + row * A_PITCHB + cc * 16,
                     vsrc + (size_t)row * D_EMB + cc * 8);
            }
        }
        loadB(g & 7, 0, 0); cp_commit();
        loadB(g & 7, 1, 1); cp_commit();

        float rs[4][2] = {{0,0},{0,0},{0,0},{0,0}};

        #pragma unroll 1
        for (int c = 0; c < cnt; c++) {
            const int buf = c & 1;
            cp_wait1();
            __syncthreads();

            const uint32_t kcB = (uint32_t)(c & 7) * 128;
            const uint32_t bOff = (uint32_t)buf * SB_BYTES;

            #pragma unroll
            for (int s = 0; s < 4; s++) {
                uint32_t ra[4][4];
                #pragma unroll
                for (int i = 0; i < 4; i++)
                    LDSM_X4(ra[i][0], ra[i][1], ra[i][2], ra[i][3],
                            aAddr[i] + kcB + s * 32);
                #pragma unroll
                for (int j2 = 0; j2 < 4; j2++) {
                    uint32_t rb0, rb1, rb2, rb3;
                    LDSM_X4(rb0, rb1, rb2, rb3, bAddr[j2] + bOff + s * 32);
                    #pragma unroll
                    for (int i = 0; i < 4; i++) {
                        MMA_BF16(acc[i][2 * j2],     ra[i][0], ra[i][1], ra[i][2], ra[i][3], rb0, rb1);
                        MMA_BF16(acc[i][2 * j2 + 1], ra[i][0], ra[i][1], ra[i][2], ra[i][3], rb2, rb3);
                    }
                }
            }

            __syncthreads();
            if (c + 2 < cnt) {
                const int c2 = c + 2;
                loadB((g + (c2 >> 3)) & 7, c2 & 7, buf);
            }
            cp_commit();

            if ((c & 7) == 7) {                        // unit done: exp rowsums
                #pragma unroll
                for (int i = 0; i < 4; i++) {
                    float a0 = 0.0f, a1 = 0.0f;
                    #pragma unroll
                    for (int j = 0; j < 8; j++) {
                        a0 += ex2a(fmaf(acc[i][j][0], c1, c0)) + ex2a(fmaf(acc[i][j][1], c1, c0));
                        a1 += ex2a(fmaf(acc[i][j][2], c1, c0)) + ex2a(fmaf(acc[i][j][3], c1, c0));
                        acc[i][j][0] = acc[i][j][1] = acc[i][j][2] = acc[i][j][3] = 0.0f;
                    }
                    rs[i][0] += a0;
                    rs[i][1] += a1;
                }
            }
        }

        // ---- flush rowsums for this mtile run -----------------------------
        #pragma unroll
        for (int i = 0; i < 4; i++)
            #pragma unroll
            for (int r = 0; r < 2; r++) {
                float x = rs[i][r];
                x += __shfl_xor_sync(0xffffffffu, x, 1);
                x += __shfl_xor_sync(0xffffffffu, x, 2);
                rs[i][r] = x;
            }
        if (t == 0) {
            #pragma unroll
            for (int i = 0; i < 4; i++)
                #pragma unroll
                for (int r = 0; r < 2; r++)
                    red[warpN * 128 + warpM * 64 + i * 16 + r * 8 + qg] = rs[i][r];
        }
        __syncthreads();
        if (tid < 128)
            atomicAdd(&g_colsum[mt * 128 + tid],
                      (red[tid] + red[128 + tid]) + (red[256 + tid] + red[384 + tid]));
        __syncthreads();                               // red/A reuse next run

        g = run_end;
    }

    // ---- fused final loss: last CTA to finish computes everything ---------
    __shared__ unsigned int srank;
    __shared__ float lsm[8];
    if (tid == 0) {
        __threadfence();
        srank = atomicAdd(&g_done, 1u);
    }
    __syncthreads();
    if (srank == GRID_GEMM - 1) {
        __threadfence();                       // see all CTAs' colsum atomics
        float L = 0.0f;
        #pragma unroll 4
        for (int j = tid; j < NM; j += 256) {
            float sd = g_sdiag[j];
            float sf = g_sself[j];
            float cs = g_colsum[j] - ex2a(fmaf(sf, c1, c0)) + ex2a(fmaf(sd, c1, c0));
            L += wv * (1.0f - sd) + __logf(cs);
        }
        #pragma unroll
        for (int o = 16; o > 0; o >>= 1) L += __shfl_xor_sync(0xffffffffu, L, o);
        if (lane == 0) lsm[wid] = L;
        __syncthreads();
        if (tid == 0) {
            float tt = 0.0f;
            #pragma unroll
            for (int w = 0; w < 8; w++) tt += lsm[w];
            *outp = tt;
            g_done = 0;                        // reset for next graph replay
        }
    }
}

// ---------------------------------------------------------------------------
extern "C" void kernel_launch(void* const* d_in, const int* in_sizes, int n_in,
                              void* d_out, int out_size) {
    const float* v  = (const float*)d_in[0];   // [NM, D] fp32
    const float* wp = (const float*)d_in[1];   // scalar w (b cancels analytically)
    float* out = (float*)d_out;

    cudaFuncSetAttribute(gemm_lse_kernel,
                         cudaFuncAttributeMaxDynamicSharedMemorySize, SMEM_SZ);

    prep_kernel<<<N_SPK, 256>>>(v);
    gemm_lse_kernel<<<GRID_GEMM, 256, SMEM_SZ>>>(wp, out);
}

// round 13
// speedup vs baseline: 1.1028x; 1.0676x over previous
#include <cuda_runtime.h>
#include <cuda_bf16.h>
#include <cstdint>
#include <math.h>

#define N_SPK 2048
#define M_UTT 16
#define D_EMB 512
#define NM (N_SPK * M_UTT)
#define EPSF 1e-8f
#define GRID_GEMM 152                  // GB300: 152 SMs, persistent 1 CTA/SM
#define NUNITS 2048                    // 256 mtiles x 8 ntiles

// ---------------- scratch (allocation-free rule: __device__ globals) -------
__device__ __nv_bfloat16 g_vnb[NM * D_EMB];     // normalized utterances, bf16
__device__ __nv_bfloat16 g_Cnb[N_SPK * D_EMB];  // normalized centroids,  bf16
__device__ float g_sdiag[NM];                   // cos(C_min[j], v_j) fp32-exact
__device__ float g_sself[NM];                   // dot of bf16-rounded Cn,vn
__device__ float g_colsum[NM];                  // sum_n exp(w*(S[n,j]-1))

// ---------------- helpers ---------------------------------------------------
__device__ __forceinline__ uint32_t smem_u32(const void* p) {
    uint32_t a;
    asm("{ .reg .u64 t; cvta.to.shared.u64 t, %1; cvt.u32.u64 %0, t; }" : "=r"(a) : "l"(p));
    return a;
}
__device__ __forceinline__ void cp16(uint32_t s, const void* g) {
    asm volatile("cp.async.cg.shared.global [%0], [%1], 16;" :: "r"(s), "l"(g) : "memory");
}
__device__ __forceinline__ void cp_commit() { asm volatile("cp.async.commit_group;" ::: "memory"); }
__device__ __forceinline__ void cp_wait1()  { asm volatile("cp.async.wait_group 1;" ::: "memory"); }
__device__ __forceinline__ float ex2a(float x) {
    float r; asm("ex2.approx.f32 %0, %1;" : "=f"(r) : "f"(x)); return r;
}
#define MMA_BF16(d, a0, a1, a2, a3, b0, b1)                                   \
    asm volatile(                                                             \
        "mma.sync.aligned.m16n8k16.row.col.f32.bf16.bf16.f32 "                \
        "{%0,%1,%2,%3}, {%4,%5,%6,%7}, {%8,%9}, {%0,%1,%2,%3};"               \
        : "+f"(d[0]), "+f"(d[1]), "+f"(d[2]), "+f"(d[3])                      \
        : "r"(a0), "r"(a1), "r"(a2), "r"(a3), "r"(b0), "r"(b1))
#define LDSM_X4(r0, r1, r2, r3, addr)                                         \
    asm volatile(                                                             \
        "ldmatrix.sync.aligned.m8n8.x4.shared.b16 {%0,%1,%2,%3}, [%4];"       \
        : "=r"(r0), "=r"(r1), "=r"(r2), "=r"(r3) : "r"(addr))

// ---------------- prep: per-speaker normalize + diag terms -----------------
__global__ __launch_bounds__(256) void prep_kernel(const float* __restrict__ v,
                                                   float* __restrict__ outp) {
    __shared__ float sv[M_UTT * D_EMB];
    __shared__ float red[8][33];
    __shared__ float fin[33];

    const int tid = threadIdx.x;
    const int n = blockIdx.x;

    if (tid < 16) g_colsum[n * 16 + tid] = 0.0f;   // zero for gemm atomics
    if (n == 0 && tid == 0) *outp = 0.0f;          // zero for loss atomics

    {
        const float4* src = (const float4*)(v + (size_t)n * M_UTT * D_EMB);
        float4* dst = (float4*)sv;
        #pragma unroll
        for (int i = 0; i < (M_UTT * D_EMB / 4) / 256; i++)
            dst[tid + i * 256] = src[tid + i * 256];
    }
    __syncthreads();

    float s0 = 0.0f, s1 = 0.0f;
    #pragma unroll
    for (int m = 0; m < M_UTT; m++) {
        s0 += sv[m * D_EMB + tid];
        s1 += sv[m * D_EMB + tid + 256];
    }

    float vals[33];
    #pragma unroll
    for (int m = 0; m < M_UTT; m++) {
        float x0 = sv[m * D_EMB + tid];
        float x1 = sv[m * D_EMB + tid + 256];
        vals[m]      = x0 * x0 + x1 * x1;
        vals[16 + m] = s0 * x0 + s1 * x1;
    }
    vals[32] = s0 * s0 + s1 * s1;

    #pragma unroll
    for (int i = 0; i < 33; i++) {
        float x = vals[i];
        #pragma unroll
        for (int o = 16; o > 0; o >>= 1) x += __shfl_xor_sync(0xffffffffu, x, o);
        vals[i] = x;
    }
    const int warp = tid >> 5, lane = tid & 31;
    if (lane == 0) {
        #pragma unroll
        for (int i = 0; i < 33; i++) red[warp][i] = vals[i];
    }
    __syncthreads();
    if (tid < 33) {
        float x = 0.0f;
        #pragma unroll
        for (int w = 0; w < 8; w++) x += red[w][tid];
        fin[tid] = x;
    }
    __syncthreads();

    const float ss = fin[32];
    const float cinv = 1.0f / fmaxf(sqrtf(ss), (float)M_UTT * EPSF);

    __nv_bfloat16 cb0 = __float2bfloat16(s0 * cinv);
    __nv_bfloat16 cb1 = __float2bfloat16(s1 * cinv);
    g_Cnb[n * D_EMB + tid]       = cb0;
    g_Cnb[n * D_EMB + tid + 256] = cb1;
    const float fc0 = __bfloat162float(cb0);
    const float fc1 = __bfloat162float(cb1);

    float sfp[16];
    #pragma unroll
    for (int m = 0; m < M_UTT; m++) {
        float rv = 1.0f / fmaxf(sqrtf(fin[m]), EPSF);
        __nv_bfloat16 vb0 = __float2bfloat16(sv[m * D_EMB + tid] * rv);
        __nv_bfloat16 vb1 = __float2bfloat16(sv[m * D_EMB + tid + 256] * rv);
        size_t base = (size_t)(n * M_UTT + m) * D_EMB;
        g_vnb[base + tid]       = vb0;
        g_vnb[base + tid + 256] = vb1;
        sfp[m] = fc0 * __bfloat162float(vb0) + fc1 * __bfloat162float(vb1);
    }

    #pragma unroll
    for (int m = 0; m < 16; m++) {
        float x = sfp[m];
        #pragma unroll
        for (int o = 16; o > 0; o >>= 1) x += __shfl_xor_sync(0xffffffffu, x, o);
        sfp[m] = x;
    }
    if (lane == 0) {
        #pragma unroll
        for (int m = 0; m < 16; m++) red[warp][m] = sfp[m];
    }
    __syncthreads();
    if (tid < 16) {
        float x = 0.0f;
        #pragma unroll
        for (int w = 0; w < 8; w++) x += red[w][tid];
        g_sself[n * M_UTT + tid] = x;

        float sq  = fin[tid];
        float dsv = fin[16 + tid];
        float nv  = fmaxf(sqrtf(sq), EPSF);
        float cm2 = fmaxf(ss - 2.0f * dsv + sq, 0.0f);
        const float invMm1 = 1.0f / (float)(M_UTT - 1);
        float ncm = fmaxf(sqrtf(cm2) * invMm1, EPSF);
        g_sdiag[n * M_UTT + tid] = ((dsv - sq) * invMm1) / (ncm * nv);
    }
}

// ---------------- persistent GEMM + fused exp rowsum ------------------------
// R8 core with register-double-buffered fragments: step s+1's LDSMs are
// issued (in volatile program order) BEFORE step s's 32 MMAs, so the MMA
// burst hides the ~30cyc LDSM latency that R11's profile exposed.
#define A_PITCHB 1040                      // bytes per A row (520 bf16)
#define B_PITCHB 144                       // bytes per B row (72 bf16)
#define SA_BYTES (128 * A_PITCHB)          // 133120
#define SB_BYTES (256 * B_PITCHB)          // 36864 per buffer
#define SB_OFF   SA_BYTES
#define SRED_OFF (SB_OFF + 2 * SB_BYTES)   // 206848
#define SMEM_SZ  (SRED_OFF + 4 * 128 * 4)  // 208896

__global__ __launch_bounds__(256, 1) void gemm_lse_kernel(const float* __restrict__ wp) {
    extern __shared__ char smem[];
    const uint32_t sbase = smem_u32(smem);
    float* red = (float*)(smem + SRED_OFF);

    const int tid = threadIdx.x;
    const int lane = tid & 31, wid = tid >> 5;
    const int warpM = wid & 1;
    const int warpN = wid >> 1;
    const int qg = lane >> 2, t = lane & 3;
    const int mat = lane >> 3, rr = lane & 7;

    const int start = (int)(((long long)blockIdx.x * NUNITS) / GRID_GEMM);
    const int end   = (int)(((long long)(blockIdx.x + 1) * NUNITS) / GRID_GEMM);

    const float wv = *wp;
    const float c1 = wv * 1.44269504f;
    const float c0 = -c1;

    uint32_t aAddr[4];
    #pragma unroll
    for (int i = 0; i < 4; i++)
        aAddr[i] = sbase + (uint32_t)(warpM * 64 + i * 16 + (mat & 1) * 8 + rr) * A_PITCHB
                 + (uint32_t)(mat >> 1) * 16;
    uint32_t bAddr[4];
    #pragma unroll
    for (int j2 = 0; j2 < 4; j2++)
        bAddr[j2] = sbase + SB_OFF
                  + (uint32_t)(warpN * 64 + j2 * 16 + (mat >> 1) * 8 + rr) * B_PITCHB
                  + (uint32_t)(mat & 1) * 16;

    auto loadB = [&](int ntile, int kc, int buf) {
        const __nv_bfloat16* bsrc = g_Cnb + (size_t)(ntile * 256) * D_EMB + kc * 64;
        const uint32_t bb = sbase + SB_OFF + buf * SB_BYTES;
        #pragma unroll
        for (int i = 0; i < 8; i++) {
            int flat = tid + 256 * i;
            int row = flat >> 3, k8 = flat & 7;
            cp16(bb + row * B_PITCHB + k8 * 16,
                 bsrc + (size_t)row * D_EMB + k8 * 8);
        }
    };

    float acc[4][8][4];
    #pragma unroll
    for (int i = 0; i < 4; i++)
        #pragma unroll
        for (int j = 0; j < 8; j++)
            #pragma unroll
            for (int r = 0; r < 4; r++) acc[i][j][r] = 0.0f;

    for (int g = start; g < end; ) {
        const int mt = g >> 3;
        const int run_end = min(end, (mt + 1) << 3);
        const int cnt = (run_end - g) * 8;

        // ---- stage A for this mtile (group with B chunk 0) ----------------
        {
            const __nv_bfloat16* vsrc = g_vnb + (size_t)(mt * 128) * D_EMB;
            #pragma unroll 8
            for (int i = 0; i < 32; i++) {
                int flat = tid + 256 * i;
                int row = flat >> 6, cc = flat & 63;
                cp16(sbase + row * A_PITCHB + cc * 16,
                     vsrc + (size_t)row * D_EMB + cc * 8);
            }
        }
        loadB(g & 7, 0, 0); cp_commit();
        loadB(g & 7, 1, 1); cp_commit();

        float rs[4][2] = {{0,0},{0,0},{0,0},{0,0}};

        #pragma unroll 1
        for (int c = 0; c < cnt; c++) {
            const int buf = c & 1;
            cp_wait1();
            __syncthreads();

            const uint32_t kcB = (uint32_t)(c & 7) * 128;
            const uint32_t bOff = (uint32_t)buf * SB_BYTES;

            // register-double-buffered fragments
            uint32_t ra[2][4][4], rb[2][4][4];
            #pragma unroll
            for (int i = 0; i < 4; i++)
                LDSM_X4(ra[0][i][0], ra[0][i][1], ra[0][i][2], ra[0][i][3],
                        aAddr[i] + kcB);
            #pragma unroll
            for (int j2 = 0; j2 < 4; j2++)
                LDSM_X4(rb[0][j2][0], rb[0][j2][1], rb[0][j2][2], rb[0][j2][3],
                        bAddr[j2] + bOff);

            #pragma unroll
            for (int s = 0; s < 4; s++) {
                const int cur = s & 1, nxt = cur ^ 1;
                if (s < 3) {                      // issue next step's LDSMs first
                    #pragma unroll
                    for (int i = 0; i < 4; i++)
                        LDSM_X4(ra[nxt][i][0], ra[nxt][i][1], ra[nxt][i][2], ra[nxt][i][3],
                                aAddr[i] + kcB + (s + 1) * 32);
                    #pragma unroll
                    for (int j2 = 0; j2 < 4; j2++)
                        LDSM_X4(rb[nxt][j2][0], rb[nxt][j2][1], rb[nxt][j2][2], rb[nxt][j2][3],
                                bAddr[j2] + bOff + (s + 1) * 32);
                }
                #pragma unroll
                for (int j2 = 0; j2 < 4; j2++)
                    #pragma unroll
                    for (int i = 0; i < 4; i++) {
                        MMA_BF16(acc[i][2 * j2],
                                 ra[cur][i][0], ra[cur][i][1], ra[cur][i][2], ra[cur][i][3],
                                 rb[cur][j2][0], rb[cur][j2][1]);
                        MMA_BF16(acc[i][2 * j2 + 1],
                                 ra[cur][i][0], ra[cur][i][1], ra[cur][i][2], ra[cur][i][3],
                                 rb[cur][j2][2], rb[cur][j2][3]);
                    }
            }

            __syncthreads();
            if (c + 2 < cnt) {
                const int c2 = c + 2;
                loadB((g + (c2 >> 3)) & 7, c2 & 7, buf);
            }
            cp_commit();

            if ((c & 7) == 7) {                    // unit done: exp rowsums
                #pragma unroll
                for (int i = 0; i < 4; i++) {
                    float a0 = 0.0f, a1 = 0.0f;
                    #pragma unroll
                    for (int j = 0; j < 8; j++) {
                        a0 += ex2a(fmaf(acc[i][j][0], c1, c0)) + ex2a(fmaf(acc[i][j][1], c1, c0));
                        a1 += ex2a(fmaf(acc[i][j][2], c1, c0)) + ex2a(fmaf(acc[i][j][3], c1, c0));
                        acc[i][j][0] = acc[i][j][1] = acc[i][j][2] = acc[i][j][3] = 0.0f;
                    }
                    rs[i][0] += a0;
                    rs[i][1] += a1;
                }
            }
        }

        // ---- flush rowsums for this mtile run -----------------------------
        #pragma unroll
        for (int i = 0; i < 4; i++)
            #pragma unroll
            for (int r = 0; r < 2; r++) {
                float x = rs[i][r];
                x += __shfl_xor_sync(0xffffffffu, x, 1);
                x += __shfl_xor_sync(0xffffffffu, x, 2);
                rs[i][r] = x;
            }
        if (t == 0) {
            #pragma unroll
            for (int i = 0; i < 4; i++)
                #pragma unroll
                for (int r = 0; r < 2; r++)
                    red[warpN * 128 + warpM * 64 + i * 16 + r * 8 + qg] = rs[i][r];
        }
        __syncthreads();
        if (tid < 128)
            atomicAdd(&g_colsum[mt * 128 + tid],
                      (red[tid] + red[128 + tid]) + (red[256 + tid] + red[384 + tid]));
        __syncthreads();

        g = run_end;
    }
}

// ---------------- final loss ------------------------------------------------
__global__ __launch_bounds__(256) void loss_kernel(const float* __restrict__ wp,
                                                   float* __restrict__ out) {
    __shared__ float rsm[8];
    const int j = blockIdx.x * blockDim.x + threadIdx.x;
    const float wv = *wp;
    const float c1 = wv * 1.44269504f;
    const float c0 = -c1;
    float L = 0.0f;
    if (j < NM) {
        float sd = g_sdiag[j];
        float sf = g_sself[j];
        float cs = g_colsum[j] - ex2a(fmaf(sf, c1, c0)) + ex2a(fmaf(sd, c1, c0));
        L = wv * (1.0f - sd) + logf(cs);
    }
    #pragma unroll
    for (int o = 16; o > 0; o >>= 1) L += __shfl_xor_sync(0xffffffffu, L, o);
    const int warp = threadIdx.x >> 5, lane = threadIdx.x & 31;
    if (lane == 0) rsm[warp] = L;
    __syncthreads();
    if (threadIdx.x == 0) {
        float tacc = 0.0f;
        #pragma unroll
        for (int w = 0; w < 8; w++) tacc += rsm[w];
        atomicAdd(out, tacc);
    }
}

// ---------------------------------------------------------------------------
extern "C" void kernel_launch(void* const* d_in, const int* in_sizes, int n_in,
                              void* d_out, int out_size) {
    const float* v  = (const float*)d_in[0];   // [NM, D] fp32
    const float* wp = (const float*)d_in[1];   // scalar w (b cancels analytically)
    float* out = (float*)d_out;

    cudaFuncSetAttribute(gemm_lse_kernel,
                         cudaFuncAttributeMaxDynamicSharedMemorySize, SMEM_SZ);

    prep_kernel<<<N_SPK, 256>>>(v, out);
    gemm_lse_kernel<<<GRID_GEMM, 256, SMEM_SZ>>>(wp);
    loss_kernel<<<NM / 256, 256>>>(wp, out);
}